// round 9
// baseline (speedup 1.0000x reference)
#include <cuda_runtime.h>
#include <cuda_bf16.h>

#define N_NODES 131072
#define NG      4096        // graphs
#define NPG     32          // nodes per graph
#define NE      1048576     // edges per branch
#define SDIM    64
#define HDIM    128
#define CAP     64          // bucket capacity per (branch, graph)

#define NB_EDGE ((2 * NE) / (256 * 4))   // 2048 edge-filter blocks
#define NB_FOLD 32                       // fold blocks appended to k1 grid

// ---------------- scratch (device globals; zero-initialized at load) --------
// Invariant: g_cnt is all-zero before every k1 launch. Initially true (module
// load zero-init); maintained because k2 re-zeroes every counter it reads.
__device__ int   g_cnt[2][NG];
__device__ int   g_bucket[2][NG][CAP];
__device__ float g_wsd[2][2][SDIM];   // [branch][{src,dst}][s] : folded W@att

// ---------------- K1: edge filter + (in extra blocks) W@att fold ------------
__global__ void k1_filter(const int* __restrict__ upE, const int* __restrict__ dnE,
                          int is64_up, int is64_dn,
                          const float* __restrict__ upW, const float* __restrict__ upAs,
                          const float* __restrict__ upAd,
                          const float* __restrict__ dnW, const float* __restrict__ dnAs,
                          const float* __restrict__ dnAd) {
    if (blockIdx.x >= NB_EDGE) {
        // fold: one warp per output scalar w[b][v][s] = sum_h W[s,h]*att[h]
        int w = (blockIdx.x - NB_EDGE) * 8 + (threadIdx.x >> 5);  // 0..255
        int l = threadIdx.x & 31;
        int b = w >> 7;
        int v = (w >> 6) & 1;
        int s = w & 63;
        const float* W = b ? dnW : upW;
        const float* a = b ? (v ? dnAd : dnAs) : (v ? upAd : upAs);
        float4 wv = ((const float4*)(W + s * HDIM))[l];
        float4 av = ((const float4*)a)[l];
        float acc = wv.x * av.x + wv.y * av.y + wv.z * av.z + wv.w * av.w;
        #pragma unroll
        for (int o = 16; o; o >>= 1) acc += __shfl_xor_sync(0xffffffffu, acc, o);
        if (l == 0) g_wsd[b][v][s] = acc;
        return;
    }

    // edge filter: 4 edges per thread, vectorized dst reads
    long long t = (long long)blockIdx.x * blockDim.x + threadIdx.x;
    long long e4 = t * 4;
    int b = (e4 >= NE) ? 1 : 0;
    long long e = e4 - (long long)b * NE;
    const int* p = b ? dnE : upE;
    int is64 = b ? is64_dn : is64_up;

    int d[4];
    if (is64) {
        // dst low words at p[2*(NE+e) + 2k]; 4 edges = 32B = two int4 loads
        const int4* q = (const int4*)(p + 2 * (NE + e));
        int4 a0 = q[0], a1 = q[1];
        d[0] = a0.x; d[1] = a0.z; d[2] = a1.x; d[3] = a1.z;
    } else {
        int4 a0 = *(const int4*)(p + NE + e);
        d[0] = a0.x; d[1] = a0.y; d[2] = a0.z; d[3] = a0.w;
    }

    int stride = is64 ? 2 : 1;
    #pragma unroll
    for (int k = 0; k < 4; k++) {
        if ((d[k] & 31) == 31) {
            int g = d[k] >> 5;
            int src = p[(e + k) * stride];
            int pos = atomicAdd(&g_cnt[b][g], 1);
            if (pos < CAP) g_bucket[b][g][pos] = src;
        }
    }
}

// ---------------- K2: per-(graph,branch) warp; batched-8 edge pipeline ------
__global__ __launch_bounds__(64) void k2_graph(
    const float* __restrict__ upx, const float* __restrict__ dnx,
    const float* __restrict__ upW, const float* __restrict__ dnW,
    const float* __restrict__ upB, const float* __restrict__ dnB,
    const float* __restrict__ mlpW, const float* __restrict__ mlpB,
    float* __restrict__ out) {

    int g = blockIdx.x;
    int b = threadIdx.x >> 5;   // warp 0 = up branch, warp 1 = down branch
    int l = threadIdx.x & 31;

    const float* x    = b ? dnx : upx;
    const float* W    = b ? dnW : upW;
    const float* bias = b ? dnB : upB;

    __shared__ int   sh_src[2][CAP];
    __shared__ float sh_xagg[2][SDIM];
    __shared__ float sh_sig[2][HDIM];

    int n = g_cnt[b][g];
    if (l == 0) g_cnt[b][g] = 0;            // restore zero-invariant for replay
    if (n > CAP) n = CAP;
    // stage bucket list in shared (one int2 per lane = 64 ints)
    ((int2*)sh_src[b])[l] = ((const int2*)g_bucket[b][g])[l];
    __syncwarp();

    // lane l owns dims {2l, 2l+1}
    float2 ws = ((const float2*)g_wsd[b][0])[l];
    float2 wd = ((const float2*)g_wsd[b][1])[l];

    // a_dst for the terminal node of this graph
    float2 xd = ((const float2*)(x + (g * NPG + NPG - 1) * SDIM))[l];
    float part = xd.x * wd.x + xd.y * wd.y;
    #pragma unroll
    for (int o = 16; o; o >>= 1) part += __shfl_xor_sync(0xffffffffu, part, o);
    float a_dst = part;

    // un-shifted softmax aggregation (logits O(10); exp safe in fp32).
    // batches of 8 edges: 8 loads issued back-to-back (MLP=8), then 8
    // interleaved butterfly chains (5-deep total instead of 5-deep per edge).
    float denom = 0.f, acc0 = 0.f, acc1 = 0.f;
    for (int base = 0; base < n; base += 8) {
        float2 xr[8];
        float  pp[8];
        #pragma unroll
        for (int j = 0; j < 8; j++) {
            int ii = base + j;
            int src = sh_src[b][ii < n ? ii : base];   // dup-safe tail
            xr[j] = ((const float2*)(x + src * SDIM))[l];
        }
        #pragma unroll
        for (int j = 0; j < 8; j++)
            pp[j] = xr[j].x * ws.x + xr[j].y * ws.y;
        #pragma unroll
        for (int o = 16; o; o >>= 1) {
            #pragma unroll
            for (int j = 0; j < 8; j++)
                pp[j] += __shfl_xor_sync(0xffffffffu, pp[j], o);
        }
        #pragma unroll
        for (int j = 0; j < 8; j++) {
            if (base + j < n) {
                float ev = pp[j] + a_dst;
                ev = ev > 0.f ? ev : 0.2f * ev;        // leaky_relu(0.2)
                float q = __expf(ev);
                denom += q;
                acc0 += q * xr[j].x;
                acc1 += q * xr[j].y;
            }
        }
    }
    float inv = 1.f / (denom + 1e-16f);

    sh_xagg[b][2 * l]     = acc0 * inv;
    sh_xagg[b][2 * l + 1] = acc1 * inv;
    __syncwarp();

    // h_out = xagg @ W: lane owns h = 4l..4l+3, one LDG.128 per s-row
    const float4* W4 = (const float4*)W;
    float4 ho = make_float4(0.f, 0.f, 0.f, 0.f);
    #pragma unroll 8
    for (int s = 0; s < SDIM; s++) {
        float xa = sh_xagg[b][s];
        float4 wv = W4[s * (HDIM / 4) + l];
        ho.x += xa * wv.x;
        ho.y += xa * wv.y;
        ho.z += xa * wv.z;
        ho.w += xa * wv.w;
    }
    float4 bv = ((const float4*)bias)[l];
    float4 sg;
    sg.x = 1.f / (1.f + __expf(-(ho.x + bv.x)));
    sg.y = 1.f / (1.f + __expf(-(ho.y + bv.y)));
    sg.z = 1.f / (1.f + __expf(-(ho.z + bv.z)));
    sg.w = 1.f / (1.f + __expf(-(ho.w + bv.w)));
    ((float4*)sh_sig[b])[l] = sg;
    __syncthreads();

    // fused epilogue: y[g] = sum_h sig_up*sig_dn*mlpW[h] + mlp_b
    if (b == 0) {
        float4 s0 = ((const float4*)sh_sig[0])[l];
        float4 s1 = ((const float4*)sh_sig[1])[l];
        float4 mw = ((const float4*)mlpW)[l];
        float s = s0.x * s1.x * mw.x + s0.y * s1.y * mw.y
                + s0.z * s1.z * mw.z + s0.w * s1.w * mw.w;
        #pragma unroll
        for (int o = 16; o; o >>= 1) s += __shfl_xor_sync(0xffffffffu, s, o);
        if (l == 0) out[g] = s + mlpB[0];
    }
}

// ---------------- launch ----------------------------------------------------
extern "C" void kernel_launch(void* const* d_in, const int* in_sizes, int n_in,
                              void* d_out, int out_size) {
    const float* up_x  = (const float*)d_in[0];
    const int*   up_e  = (const int*)  d_in[1];
    const float* dn_x  = (const float*)d_in[3];
    const int*   dn_e  = (const int*)  d_in[4];
    const float* upW   = (const float*)d_in[6];
    const float* upAs  = (const float*)d_in[7];
    const float* upAd  = (const float*)d_in[8];
    const float* upB   = (const float*)d_in[9];
    const float* dnW   = (const float*)d_in[10];
    const float* dnAs  = (const float*)d_in[11];
    const float* dnAd  = (const float*)d_in[12];
    const float* dnB   = (const float*)d_in[13];
    const float* mlpW  = (const float*)d_in[14];
    const float* mlpB  = (const float*)d_in[15];
    float* out = (float*)d_out;

    // int64 edge tensors arrive as int32 words with doubled element count:
    // 2*2*NE = 4*NE words vs 2*NE for true int32.
    int is64_up = (in_sizes[1] >= 4 * NE) ? 1 : 0;
    int is64_dn = (in_sizes[4] >= 4 * NE) ? 1 : 0;

    k1_filter<<<NB_EDGE + NB_FOLD, 256>>>(up_e, dn_e, is64_up, is64_dn,
                                          upW, upAs, upAd, dnW, dnAs, dnAd);
    k2_graph<<<NG, 64>>>(up_x, dn_x, upW, dnW, upB, dnB, mlpW, mlpB, out);
}

// round 10
// speedup vs baseline: 1.1359x; 1.1359x over previous
#include <cuda_runtime.h>
#include <cuda_bf16.h>

#define N_NODES 131072
#define NG      4096        // graphs
#define NPG     32          // nodes per graph
#define NE      1048576     // edges per branch
#define SDIM    64
#define HDIM    128
#define CAP     64          // bucket capacity per (branch, graph)

#define NB_EDGE ((2 * NE) / (256 * 4))   // 2048 edge-filter blocks
#define NB_FOLD 32                       // fold blocks appended to k1 grid

// ---------------- scratch (device globals; zero-initialized at load) --------
// Invariant: g_cnt is all-zero before every k1 launch. Initially true (module
// load zero-init); maintained because k2 re-zeroes every counter it reads.
__device__ int   g_cnt[2][NG];
__device__ int   g_bucket[2][NG][CAP];
__device__ float g_wsd[2][2][SDIM];   // [branch][{src,dst}][s] : folded W@att

// ---------------- K1: edge filter + (in extra blocks) W@att fold ------------
__global__ void k1_filter(const int* __restrict__ upE, const int* __restrict__ dnE,
                          int is64_up, int is64_dn,
                          const float* __restrict__ upW, const float* __restrict__ upAs,
                          const float* __restrict__ upAd,
                          const float* __restrict__ dnW, const float* __restrict__ dnAs,
                          const float* __restrict__ dnAd) {
    if (blockIdx.x >= NB_EDGE) {
        // fold: one warp per output scalar w[b][v][s] = sum_h W[s,h]*att[h]
        int w = (blockIdx.x - NB_EDGE) * 8 + (threadIdx.x >> 5);  // 0..255
        int l = threadIdx.x & 31;
        int b = w >> 7;
        int v = (w >> 6) & 1;
        int s = w & 63;
        const float* W = b ? dnW : upW;
        const float* a = b ? (v ? dnAd : dnAs) : (v ? upAd : upAs);
        float4 wv = ((const float4*)(W + s * HDIM))[l];
        float4 av = ((const float4*)a)[l];
        float acc = wv.x * av.x + wv.y * av.y + wv.z * av.z + wv.w * av.w;
        #pragma unroll
        for (int o = 16; o; o >>= 1) acc += __shfl_xor_sync(0xffffffffu, acc, o);
        if (l == 0) g_wsd[b][v][s] = acc;
        return;
    }

    // edge filter: 4 edges per thread, vectorized dst reads
    long long t = (long long)blockIdx.x * blockDim.x + threadIdx.x;
    long long e4 = t * 4;
    int b = (e4 >= NE) ? 1 : 0;
    long long e = e4 - (long long)b * NE;
    const int* p = b ? dnE : upE;
    int is64 = b ? is64_dn : is64_up;

    int d[4];
    if (is64) {
        // dst low words at p[2*(NE+e) + 2k]; 4 edges = 32B = two int4 loads
        const int4* q = (const int4*)(p + 2 * (NE + e));
        int4 a0 = q[0], a1 = q[1];
        d[0] = a0.x; d[1] = a0.z; d[2] = a1.x; d[3] = a1.z;
    } else {
        int4 a0 = *(const int4*)(p + NE + e);
        d[0] = a0.x; d[1] = a0.y; d[2] = a0.z; d[3] = a0.w;
    }

    int stride = is64 ? 2 : 1;
    #pragma unroll
    for (int k = 0; k < 4; k++) {
        if ((d[k] & 31) == 31) {
            int g = d[k] >> 5;
            int src = p[(e + k) * stride];
            int pos = atomicAdd(&g_cnt[b][g], 1);
            if (pos < CAP) g_bucket[b][g][pos] = src;
        }
    }
}

// ---------------- K2: 4 warps per graph; 2 warps split each branch's edges --
__global__ __launch_bounds__(128) void k2_graph(
    const float* __restrict__ upx, const float* __restrict__ dnx,
    const float* __restrict__ upW, const float* __restrict__ dnW,
    const float* __restrict__ upB, const float* __restrict__ dnB,
    const float* __restrict__ mlpW, const float* __restrict__ mlpB,
    float* __restrict__ out) {

    int g = blockIdx.x;
    int w = threadIdx.x >> 5;
    int l = threadIdx.x & 31;
    int b    = w >> 1;          // warps {0,1}: up, warps {2,3}: down
    int half = w & 1;           // even/odd edge split within the branch

    const float* x = b ? dnx : upx;

    __shared__ int   sh_src[2][CAP];
    __shared__ float sh_xagg[2][SDIM];
    __shared__ float sh_sig[2][HDIM];
    __shared__ float sh_pacc[2][SDIM];
    __shared__ float sh_pden[2];
    __shared__ int   sh_n[2];

    if (half == 0) {
        int n = g_cnt[b][g];
        if (l == 0) { g_cnt[b][g] = 0;              // restore zero-invariant
                      sh_n[b] = n > CAP ? CAP : n; }
        ((int2*)sh_src[b])[l] = ((const int2*)g_bucket[b][g])[l];
    }
    __syncthreads();
    int n = sh_n[b];

    // folded attention weights: lane l owns dims {l, l+32}
    float ws0 = g_wsd[b][0][l], ws1 = g_wsd[b][0][l + 32];
    float wd0 = g_wsd[b][1][l], wd1 = g_wsd[b][1][l + 32];

    // a_dst for the terminal node (computed redundantly by both branch warps)
    int dnode = g * NPG + (NPG - 1);
    float xd0 = x[dnode * SDIM + l];
    float xd1 = x[dnode * SDIM + 32 + l];
    float part = xd0 * wd0 + xd1 * wd1;
    #pragma unroll
    for (int o = 16; o; o >>= 1) part += __shfl_xor_sync(0xffffffffu, part, o);
    float a_dst = part;

    // un-shifted softmax aggregation over this warp's half of the edges
    // (logits O(10); exp safe in fp32)
    float denom = 0.f, acc0 = 0.f, acc1 = 0.f;
    for (int i = half; i < n; i += 2) {
        int src = sh_src[b][i];
        float xv0 = x[src * SDIM + l];
        float xv1 = x[src * SDIM + 32 + l];
        float ps = xv0 * ws0 + xv1 * ws1;
        #pragma unroll
        for (int o = 16; o; o >>= 1) ps += __shfl_xor_sync(0xffffffffu, ps, o);
        float ev = ps + a_dst;
        ev = ev > 0.f ? ev : 0.2f * ev;            // leaky_relu(0.2)
        float q = __expf(ev);
        denom += q;
        acc0 += q * xv0;
        acc1 += q * xv1;
    }
    // combine the two halves through smem
    if (half == 1) {
        sh_pacc[b][l]      = acc0;
        sh_pacc[b][l + 32] = acc1;
        if (l == 0) sh_pden[b] = denom;
    }
    __syncthreads();
    if (half == 0) {
        acc0  += sh_pacc[b][l];
        acc1  += sh_pacc[b][l + 32];
        denom += sh_pden[b];
        float inv = 1.f / (denom + 1e-16f);
        sh_xagg[b][l]      = acc0 * inv;
        sh_xagg[b][l + 32] = acc1 * inv;
    }
    __syncthreads();

    // GEMV: warp w owns h = l + 32w, computes BOTH branches' outputs
    {
        int h = l + 32 * w;
        float ho0 = 0.f, ho1 = 0.f;
        #pragma unroll 8
        for (int s = 0; s < SDIM; s++) {
            ho0 += sh_xagg[0][s] * upW[s * HDIM + h];
            ho1 += sh_xagg[1][s] * dnW[s * HDIM + h];
        }
        sh_sig[0][h] = 1.f / (1.f + __expf(-(ho0 + upB[h])));
        sh_sig[1][h] = 1.f / (1.f + __expf(-(ho1 + dnB[h])));
    }
    __syncthreads();

    // fused epilogue: y[g] = sum_h sig_up*sig_dn*mlpW[h] + mlp_b
    if (w == 0) {
        float4 s0 = ((const float4*)sh_sig[0])[l];
        float4 s1 = ((const float4*)sh_sig[1])[l];
        float4 mw = ((const float4*)mlpW)[l];
        float s = s0.x * s1.x * mw.x + s0.y * s1.y * mw.y
                + s0.z * s1.z * mw.z + s0.w * s1.w * mw.w;
        #pragma unroll
        for (int o = 16; o; o >>= 1) s += __shfl_xor_sync(0xffffffffu, s, o);
        if (l == 0) out[g] = s + mlpB[0];
    }
}

// ---------------- launch ----------------------------------------------------
extern "C" void kernel_launch(void* const* d_in, const int* in_sizes, int n_in,
                              void* d_out, int out_size) {
    const float* up_x  = (const float*)d_in[0];
    const int*   up_e  = (const int*)  d_in[1];
    const float* dn_x  = (const float*)d_in[3];
    const int*   dn_e  = (const int*)  d_in[4];
    const float* upW   = (const float*)d_in[6];
    const float* upAs  = (const float*)d_in[7];
    const float* upAd  = (const float*)d_in[8];
    const float* upB   = (const float*)d_in[9];
    const float* dnW   = (const float*)d_in[10];
    const float* dnAs  = (const float*)d_in[11];
    const float* dnAd  = (const float*)d_in[12];
    const float* dnB   = (const float*)d_in[13];
    const float* mlpW  = (const float*)d_in[14];
    const float* mlpB  = (const float*)d_in[15];
    float* out = (float*)d_out;

    // int64 edge tensors arrive as int32 words with doubled element count:
    // 2*2*NE = 4*NE words vs 2*NE for true int32.
    int is64_up = (in_sizes[1] >= 4 * NE) ? 1 : 0;
    int is64_dn = (in_sizes[4] >= 4 * NE) ? 1 : 0;

    k1_filter<<<NB_EDGE + NB_FOLD, 256>>>(up_e, dn_e, is64_up, is64_dn,
                                          upW, upAs, upAd, dnW, dnAs, dnAd);
    k2_graph<<<NG, 128>>>(up_x, dn_x, upW, dnW, upB, dnB, mlpW, mlpB, out);
}

// round 11
// speedup vs baseline: 1.2513x; 1.1016x over previous
#include <cuda_runtime.h>
#include <cuda_bf16.h>

#define N_NODES 131072
#define NG      4096        // graphs
#define NPG     32          // nodes per graph
#define NE      1048576     // edges per branch
#define SDIM    64
#define HDIM    128
#define CAP     64          // bucket capacity per (branch, graph)

#define NB_EDGE ((2 * NE) / (256 * 4))   // 2048 edge-filter blocks
#define NB_FOLD 32                       // fold blocks appended to k1 grid
#define GPB     8                        // graphs per k2b block

// ---------------- scratch (device globals; zero-initialized at load) --------
// Invariant: g_cnt is all-zero before every k1 launch. Initially true (module
// load zero-init); maintained because k2a re-zeroes every counter it reads.
__device__ int   g_cnt[2][NG];
__device__ int   g_bucket[2][NG][CAP];
__device__ float g_wsd[2][2][SDIM];     // [branch][{src,dst}][s] : folded W@att
__device__ float g_xagg[2][NG][SDIM];   // branch aggregation results

// ---------------- K1: edge filter + (in extra blocks) W@att fold ------------
__global__ void k1_filter(const int* __restrict__ upE, const int* __restrict__ dnE,
                          int is64_up, int is64_dn,
                          const float* __restrict__ upW, const float* __restrict__ upAs,
                          const float* __restrict__ upAd,
                          const float* __restrict__ dnW, const float* __restrict__ dnAs,
                          const float* __restrict__ dnAd) {
    if (blockIdx.x >= NB_EDGE) {
        // fold: one warp per output scalar w[b][v][s] = sum_h W[s,h]*att[h]
        int w = (blockIdx.x - NB_EDGE) * 8 + (threadIdx.x >> 5);  // 0..255
        int l = threadIdx.x & 31;
        int b = w >> 7;
        int v = (w >> 6) & 1;
        int s = w & 63;
        const float* W = b ? dnW : upW;
        const float* a = b ? (v ? dnAd : dnAs) : (v ? upAd : upAs);
        float4 wv = ((const float4*)(W + s * HDIM))[l];
        float4 av = ((const float4*)a)[l];
        float acc = wv.x * av.x + wv.y * av.y + wv.z * av.z + wv.w * av.w;
        #pragma unroll
        for (int o = 16; o; o >>= 1) acc += __shfl_xor_sync(0xffffffffu, acc, o);
        if (l == 0) g_wsd[b][v][s] = acc;
        return;
    }

    // edge filter: 4 edges per thread, vectorized dst reads
    long long t = (long long)blockIdx.x * blockDim.x + threadIdx.x;
    long long e4 = t * 4;
    int b = (e4 >= NE) ? 1 : 0;
    long long e = e4 - (long long)b * NE;
    const int* p = b ? dnE : upE;
    int is64 = b ? is64_dn : is64_up;

    int d[4];
    if (is64) {
        // dst low words at p[2*(NE+e) + 2k]; 4 edges = 32B = two int4 loads
        const int4* q = (const int4*)(p + 2 * (NE + e));
        int4 a0 = q[0], a1 = q[1];
        d[0] = a0.x; d[1] = a0.z; d[2] = a1.x; d[3] = a1.z;
    } else {
        int4 a0 = *(const int4*)(p + NE + e);
        d[0] = a0.x; d[1] = a0.y; d[2] = a0.z; d[3] = a0.w;
    }

    int stride = is64 ? 2 : 1;
    #pragma unroll
    for (int k = 0; k < 4; k++) {
        if ((d[k] & 31) == 31) {
            int g = d[k] >> 5;
            int src = p[(e + k) * stride];
            int pos = atomicAdd(&g_cnt[b][g], 1);
            if (pos < CAP) g_bucket[b][g][pos] = src;
        }
    }
}

// ---------------- K2a: per-(graph,branch) warp softmax aggregation ----------
// Pure edge phase (the latency-bound part) at maximum warp parallelism.
__global__ __launch_bounds__(64) void k2a_agg(
    const float* __restrict__ upx, const float* __restrict__ dnx) {

    int g = blockIdx.x;
    int b = threadIdx.x >> 5;   // warp 0 = up branch, warp 1 = down branch
    int l = threadIdx.x & 31;

    const float* x = b ? dnx : upx;

    __shared__ int sh_src[2][CAP];

    int n = g_cnt[b][g];
    if (l == 0) g_cnt[b][g] = 0;            // restore zero-invariant for replay
    if (n > CAP) n = CAP;
    ((int2*)sh_src[b])[l] = ((const int2*)g_bucket[b][g])[l];
    __syncwarp();

    // folded attention weights: lane l owns dims {l, l+32}
    float ws0 = g_wsd[b][0][l], ws1 = g_wsd[b][0][l + 32];
    float wd0 = g_wsd[b][1][l], wd1 = g_wsd[b][1][l + 32];

    // a_dst for the terminal node of this graph
    int dnode = g * NPG + (NPG - 1);
    float xd0 = x[dnode * SDIM + l];
    float xd1 = x[dnode * SDIM + 32 + l];
    float part = xd0 * wd0 + xd1 * wd1;
    #pragma unroll
    for (int o = 16; o; o >>= 1) part += __shfl_xor_sync(0xffffffffu, part, o);
    float a_dst = part;

    // un-shifted softmax aggregation (logits O(10); exp safe in fp32)
    float denom = 0.f, acc0 = 0.f, acc1 = 0.f;
    for (int i = 0; i < n; i++) {
        int src = sh_src[b][i];
        float xv0 = x[src * SDIM + l];
        float xv1 = x[src * SDIM + 32 + l];
        float ps = xv0 * ws0 + xv1 * ws1;
        #pragma unroll
        for (int o = 16; o; o >>= 1) ps += __shfl_xor_sync(0xffffffffu, ps, o);
        float ev = ps + a_dst;
        ev = ev > 0.f ? ev : 0.2f * ev;        // leaky_relu(0.2)
        float q = __expf(ev);
        denom += q;
        acc0 += q * xv0;
        acc1 += q * xv1;
    }
    float inv = 1.f / (denom + 1e-16f);
    g_xagg[b][g][l]      = acc0 * inv;
    g_xagg[b][g][l + 32] = acc1 * inv;
}

// ---------------- K2b: batched GEMV + sigmoid + fused mlp epilogue ----------
// Each thread owns (branch, h) and FMAs each W element against GPB graphs:
// W-load instruction count drops GPB x vs per-graph GEMV.
__global__ __launch_bounds__(256) void k2b_gemm(
    const float* __restrict__ upW, const float* __restrict__ dnW,
    const float* __restrict__ upB, const float* __restrict__ dnB,
    const float* __restrict__ mlpW, const float* __restrict__ mlpB,
    float* __restrict__ out) {

    int g0 = blockIdx.x * GPB;
    int t  = threadIdx.x;

    __shared__ float xt[2][SDIM][GPB];     // transposed xagg slab (4KB)
    __shared__ float sig[2][GPB][HDIM];    // sigmoid outputs (8KB)

    // load 2*GPB*SDIM = 1024 floats (4 per thread), transpose into smem
    #pragma unroll
    for (int k = 0; k < (2 * GPB * SDIM) / 256; k++) {
        int idx = t + 256 * k;
        int b  = idx >> 9;            // /(GPB*SDIM)
        int r  = idx & 511;
        int gi = r >> 6;
        int s  = r & 63;
        xt[b][s][gi] = g_xagg[b][g0 + gi][s];
    }
    __syncthreads();

    // GEMV: thread owns (b, h); 8 accumulators over the block's graphs
    {
        int b = t >> 7;
        int h = t & 127;
        const float* W = b ? dnW : upW;
        float bv = (b ? dnB : upB)[h];

        float ho[GPB];
        #pragma unroll
        for (int gi = 0; gi < GPB; gi++) ho[gi] = 0.f;

        #pragma unroll 8
        for (int s = 0; s < SDIM; s++) {
            float wv = W[s * HDIM + h];              // coalesced, L1/L2-hot
            float4 xa = *(const float4*)&xt[b][s][0];  // broadcast LDS
            float4 xb = *(const float4*)&xt[b][s][4];
            ho[0] += wv * xa.x; ho[1] += wv * xa.y;
            ho[2] += wv * xa.z; ho[3] += wv * xa.w;
            ho[4] += wv * xb.x; ho[5] += wv * xb.y;
            ho[6] += wv * xb.z; ho[7] += wv * xb.w;
        }
        #pragma unroll
        for (int gi = 0; gi < GPB; gi++)
            sig[b][gi][h] = 1.f / (1.f + __expf(-(ho[gi] + bv)));
    }
    __syncthreads();

    // fused epilogue: warp w handles graph g0+w
    int w = t >> 5, l = t & 31;
    float4 s0 = ((const float4*)sig[0][w])[l];
    float4 s1 = ((const float4*)sig[1][w])[l];
    float4 mw = ((const float4*)mlpW)[l];
    float s = s0.x * s1.x * mw.x + s0.y * s1.y * mw.y
            + s0.z * s1.z * mw.z + s0.w * s1.w * mw.w;
    #pragma unroll
    for (int o = 16; o; o >>= 1) s += __shfl_xor_sync(0xffffffffu, s, o);
    if (l == 0) out[g0 + w] = s + mlpB[0];
}

// ---------------- launch ----------------------------------------------------
extern "C" void kernel_launch(void* const* d_in, const int* in_sizes, int n_in,
                              void* d_out, int out_size) {
    const float* up_x  = (const float*)d_in[0];
    const int*   up_e  = (const int*)  d_in[1];
    const float* dn_x  = (const float*)d_in[3];
    const int*   dn_e  = (const int*)  d_in[4];
    const float* upW   = (const float*)d_in[6];
    const float* upAs  = (const float*)d_in[7];
    const float* upAd  = (const float*)d_in[8];
    const float* upB   = (const float*)d_in[9];
    const float* dnW   = (const float*)d_in[10];
    const float* dnAs  = (const float*)d_in[11];
    const float* dnAd  = (const float*)d_in[12];
    const float* dnB   = (const float*)d_in[13];
    const float* mlpW  = (const float*)d_in[14];
    const float* mlpB  = (const float*)d_in[15];
    float* out = (float*)d_out;

    // int64 edge tensors arrive as int32 words with doubled element count:
    // 2*2*NE = 4*NE words vs 2*NE for true int32.
    int is64_up = (in_sizes[1] >= 4 * NE) ? 1 : 0;
    int is64_dn = (in_sizes[4] >= 4 * NE) ? 1 : 0;

    k1_filter<<<NB_EDGE + NB_FOLD, 256>>>(up_e, dn_e, is64_up, is64_dn,
                                          upW, upAs, upAd, dnW, dnAs, dnAd);
    k2a_agg<<<NG, 64>>>(up_x, dn_x);
    k2b_gemm<<<NG / GPB, 256>>>(upW, dnW, upB, dnB, mlpW, mlpB, out);
}

// round 12
// speedup vs baseline: 1.7016x; 1.3599x over previous
#include <cuda_runtime.h>
#include <cuda_bf16.h>

#define N_NODES 131072
#define NG      4096        // graphs
#define NPG     32          // nodes per graph
#define NE      1048576     // edges per branch
#define SDIM    64
#define HDIM    128
#define CAP     64          // bucket capacity per (branch, graph)

#define NB_EDGE ((2 * NE) / (256 * 4))   // 2048 edge-filter blocks
#define NB_FOLD 32                       // fold blocks appended to k1 grid
#define GPB     8                        // graphs per k2 block

// ---------------- scratch (device globals; zero-initialized at load) --------
// Invariant: g_cnt is all-zero before every k1 launch. Initially true (module
// load zero-init); maintained because k2 re-zeroes every counter it reads.
__device__ int   g_cnt[2][NG];
__device__ int   g_bucket[2][NG][CAP];
__device__ float g_wsd[2][2][SDIM];     // [branch][{src,dst}][s] : folded W@att

// ---------------- K1: edge filter + (in extra blocks) W@att fold ------------
__global__ void k1_filter(const int* __restrict__ upE, const int* __restrict__ dnE,
                          int is64_up, int is64_dn,
                          const float* __restrict__ upW, const float* __restrict__ upAs,
                          const float* __restrict__ upAd,
                          const float* __restrict__ dnW, const float* __restrict__ dnAs,
                          const float* __restrict__ dnAd) {
    if (blockIdx.x >= NB_EDGE) {
        // fold: one warp per output scalar w[b][v][s] = sum_h W[s,h]*att[h]
        int w = (blockIdx.x - NB_EDGE) * 8 + (threadIdx.x >> 5);  // 0..255
        int l = threadIdx.x & 31;
        int b = w >> 7;
        int v = (w >> 6) & 1;
        int s = w & 63;
        const float* W = b ? dnW : upW;
        const float* a = b ? (v ? dnAd : dnAs) : (v ? upAd : upAs);
        float4 wv = ((const float4*)(W + s * HDIM))[l];
        float4 av = ((const float4*)a)[l];
        float acc = wv.x * av.x + wv.y * av.y + wv.z * av.z + wv.w * av.w;
        #pragma unroll
        for (int o = 16; o; o >>= 1) acc += __shfl_xor_sync(0xffffffffu, acc, o);
        if (l == 0) g_wsd[b][v][s] = acc;
        return;
    }

    // edge filter: 4 edges per thread, vectorized dst reads
    long long t = (long long)blockIdx.x * blockDim.x + threadIdx.x;
    long long e4 = t * 4;
    int b = (e4 >= NE) ? 1 : 0;
    long long e = e4 - (long long)b * NE;
    const int* p = b ? dnE : upE;
    int is64 = b ? is64_dn : is64_up;

    int d[4];
    if (is64) {
        // dst low words at p[2*(NE+e) + 2k]; 4 edges = 32B = two int4 loads
        const int4* q = (const int4*)(p + 2 * (NE + e));
        int4 a0 = q[0], a1 = q[1];
        d[0] = a0.x; d[1] = a0.z; d[2] = a1.x; d[3] = a1.z;
    } else {
        int4 a0 = *(const int4*)(p + NE + e);
        d[0] = a0.x; d[1] = a0.y; d[2] = a0.z; d[3] = a0.w;
    }

    int stride = is64 ? 2 : 1;
    #pragma unroll
    for (int k = 0; k < 4; k++) {
        if ((d[k] & 31) == 31) {
            int g = d[k] >> 5;
            int src = p[(e + k) * stride];
            int pos = atomicAdd(&g_cnt[b][g], 1);
            if (pos < CAP) g_bucket[b][g][pos] = src;
        }
    }
}

// ---------------- K2: fused. 512 thr = 16 agg warps (1 task each) + batched
// GEMV over 8 graphs + fused epilogue. launch_bounds(512,4) => <=32 regs =>
// 2048 thr/SM: all 8192 agg tasks run in wave 1 at one-task-per-warp.
__global__ __launch_bounds__(512, 4) void k2_fused(
    const float* __restrict__ upx, const float* __restrict__ dnx,
    const float* __restrict__ upW, const float* __restrict__ dnW,
    const float* __restrict__ upB, const float* __restrict__ dnB,
    const float* __restrict__ mlpW, const float* __restrict__ mlpB,
    float* __restrict__ out) {

    int g0 = blockIdx.x * GPB;
    int t  = threadIdx.x;
    int w  = t >> 5;
    int l  = t & 31;

    __shared__ int   sh_src[16][CAP];        // 4KB
    __shared__ float xt[2][SDIM][GPB];       // 4KB transposed xagg
    __shared__ float sig[2][GPB][HDIM];      // 8KB sigmoid outputs

    // ---- phase 1: aggregation, one (branch, graph) task per warp ----
    {
        int b  = w >> 3;                     // warps 0-7: up, 8-15: down
        int gi = w & 7;
        int g  = g0 + gi;
        const float* x = b ? dnx : upx;

        int n = g_cnt[b][g];
        if (l == 0) g_cnt[b][g] = 0;         // restore zero-invariant
        if (n > CAP) n = CAP;
        ((int2*)sh_src[w])[l] = ((const int2*)g_bucket[b][g])[l];
        __syncwarp();

        // folded attention weights: lane l owns dims {l, l+32}
        float ws0 = g_wsd[b][0][l], ws1 = g_wsd[b][0][l + 32];
        float wd0 = g_wsd[b][1][l], wd1 = g_wsd[b][1][l + 32];

        // a_dst for the terminal node of this graph
        int dnode = g * NPG + (NPG - 1);
        float xd0 = x[dnode * SDIM + l];
        float xd1 = x[dnode * SDIM + 32 + l];
        float part = xd0 * wd0 + xd1 * wd1;
        #pragma unroll
        for (int o = 16; o; o >>= 1) part += __shfl_xor_sync(0xffffffffu, part, o);
        float a_dst = part;

        // un-shifted softmax aggregation (logits O(10); exp safe in fp32)
        float denom = 0.f, acc0 = 0.f, acc1 = 0.f;
        for (int i = 0; i < n; i++) {
            int src = sh_src[w][i];
            float xv0 = x[src * SDIM + l];
            float xv1 = x[src * SDIM + 32 + l];
            float ps = xv0 * ws0 + xv1 * ws1;
            #pragma unroll
            for (int o = 16; o; o >>= 1) ps += __shfl_xor_sync(0xffffffffu, ps, o);
            float ev = ps + a_dst;
            ev = ev > 0.f ? ev : 0.2f * ev;  // leaky_relu(0.2)
            float q = __expf(ev);
            denom += q;
            acc0 += q * xv0;
            acc1 += q * xv1;
        }
        float inv = 1.f / (denom + 1e-16f);
        xt[b][l][gi]      = acc0 * inv;      // transposed for batched GEMV
        xt[b][l + 32][gi] = acc1 * inv;
    }
    __syncthreads();

    // ---- phase 2: batched GEMV. thread t<256 owns (b, h); each W element
    // loaded once and FMAed against all 8 graphs (8x fewer W-load instrs) ----
    if (t < 256) {
        int b = t >> 7;
        int h = t & 127;
        const float* W = b ? dnW : upW;
        float bv = (b ? dnB : upB)[h];

        float ho[GPB];
        #pragma unroll
        for (int gi = 0; gi < GPB; gi++) ho[gi] = 0.f;

        #pragma unroll 8
        for (int s = 0; s < SDIM; s++) {
            float wv = W[s * HDIM + h];               // coalesced
            float4 xa = *(const float4*)&xt[b][s][0]; // broadcast LDS
            float4 xb = *(const float4*)&xt[b][s][4];
            ho[0] += wv * xa.x; ho[1] += wv * xa.y;
            ho[2] += wv * xa.z; ho[3] += wv * xa.w;
            ho[4] += wv * xb.x; ho[5] += wv * xb.y;
            ho[6] += wv * xb.z; ho[7] += wv * xb.w;
        }
        #pragma unroll
        for (int gi = 0; gi < GPB; gi++)
            sig[b][gi][h] = 1.f / (1.f + __expf(-(ho[gi] + bv)));
    }
    __syncthreads();

    // ---- phase 3: fused epilogue, warps 0..7 -> graph g0+w ----
    if (w < GPB) {
        float4 s0 = ((const float4*)sig[0][w])[l];
        float4 s1 = ((const float4*)sig[1][w])[l];
        float4 mw = ((const float4*)mlpW)[l];
        float s = s0.x * s1.x * mw.x + s0.y * s1.y * mw.y
                + s0.z * s1.z * mw.z + s0.w * s1.w * mw.w;
        #pragma unroll
        for (int o = 16; o; o >>= 1) s += __shfl_xor_sync(0xffffffffu, s, o);
        if (l == 0) out[g0 + w] = s + mlpB[0];
    }
}

// ---------------- launch ----------------------------------------------------
extern "C" void kernel_launch(void* const* d_in, const int* in_sizes, int n_in,
                              void* d_out, int out_size) {
    const float* up_x  = (const float*)d_in[0];
    const int*   up_e  = (const int*)  d_in[1];
    const float* dn_x  = (const float*)d_in[3];
    const int*   dn_e  = (const int*)  d_in[4];
    const float* upW   = (const float*)d_in[6];
    const float* upAs  = (const float*)d_in[7];
    const float* upAd  = (const float*)d_in[8];
    const float* upB   = (const float*)d_in[9];
    const float* dnW   = (const float*)d_in[10];
    const float* dnAs  = (const float*)d_in[11];
    const float* dnAd  = (const float*)d_in[12];
    const float* dnB   = (const float*)d_in[13];
    const float* mlpW  = (const float*)d_in[14];
    const float* mlpB  = (const float*)d_in[15];
    float* out = (float*)d_out;

    // int64 edge tensors arrive as int32 words with doubled element count:
    // 2*2*NE = 4*NE words vs 2*NE for true int32.
    int is64_up = (in_sizes[1] >= 4 * NE) ? 1 : 0;
    int is64_dn = (in_sizes[4] >= 4 * NE) ? 1 : 0;

    k1_filter<<<NB_EDGE + NB_FOLD, 256>>>(up_e, dn_e, is64_up, is64_dn,
                                          upW, upAs, upAd, dnW, dnAs, dnAd);
    k2_fused<<<NG / GPB, 512>>>(up_x, dn_x, upW, dnW, upB, dnB, mlpW, mlpB, out);
}

// round 13
// speedup vs baseline: 1.9929x; 1.1712x over previous
#include <cuda_runtime.h>
#include <cuda_bf16.h>

#define N_NODES 131072
#define NG      4096        // graphs
#define NPG     32          // nodes per graph
#define NE      1048576     // edges per branch
#define SDIM    64
#define HDIM    128
#define CAP     64          // bucket capacity per (branch, graph)

#define EPT     8                        // edges per thread in k1
#define NB_EDGE ((2 * NE) / (256 * EPT)) // 1024 edge-filter blocks
#define NB_FOLD 32                       // fold blocks appended to k1 grid
#define GPB     8                        // graphs per k2 block

// ---------------- scratch (device globals; zero-initialized at load) --------
// Invariant: g_cnt is all-zero before every k1 launch. Initially true (module
// load zero-init); maintained because k2 re-zeroes every counter it reads.
__device__ int   g_cnt[2][NG];
__device__ int   g_bucket[2][NG][CAP];
__device__ float g_wsd[2][2][SDIM];     // [branch][{src,dst}][s] : folded W@att

// ---------------- K1: edge filter + (in extra blocks) W@att fold ------------
__global__ void k1_filter(const int* __restrict__ upE, const int* __restrict__ dnE,
                          int is64_up, int is64_dn,
                          const float* __restrict__ upW, const float* __restrict__ upAs,
                          const float* __restrict__ upAd,
                          const float* __restrict__ dnW, const float* __restrict__ dnAs,
                          const float* __restrict__ dnAd) {
    if (blockIdx.x >= NB_EDGE) {
        // fold: one warp per output scalar w[b][v][s] = sum_h W[s,h]*att[h]
        int w = (blockIdx.x - NB_EDGE) * 8 + (threadIdx.x >> 5);  // 0..255
        int l = threadIdx.x & 31;
        int b = w >> 7;
        int v = (w >> 6) & 1;
        int s = w & 63;
        const float* W = b ? dnW : upW;
        const float* a = b ? (v ? dnAd : dnAs) : (v ? upAd : upAs);
        float4 wv = ((const float4*)(W + s * HDIM))[l];
        float4 av = ((const float4*)a)[l];
        float acc = wv.x * av.x + wv.y * av.y + wv.z * av.z + wv.w * av.w;
        #pragma unroll
        for (int o = 16; o; o >>= 1) acc += __shfl_xor_sync(0xffffffffu, acc, o);
        if (l == 0) g_wsd[b][v][s] = acc;
        return;
    }

    // edge filter: EPT=8 edges per thread, 4x LDG.128 dst scan (high MLP)
    long long t = (long long)blockIdx.x * blockDim.x + threadIdx.x;
    long long e8 = t * EPT;
    int b = (e8 >= NE) ? 1 : 0;          // blocks never straddle the branch
    long long e = e8 - (long long)b * NE;
    const int* p = b ? dnE : upE;
    int is64 = b ? is64_dn : is64_up;

    int d[EPT];
    if (is64) {
        const int4* q = (const int4*)(p + 2 * (NE + e));  // 8 edges = 64B
        #pragma unroll
        for (int j = 0; j < 4; j++) {
            int4 a = q[j];
            d[2 * j]     = a.x;
            d[2 * j + 1] = a.z;
        }
    } else {
        const int4* q = (const int4*)(p + NE + e);        // 8 edges = 32B
        #pragma unroll
        for (int j = 0; j < 2; j++) {
            int4 a = q[j];
            d[4 * j]     = a.x;
            d[4 * j + 1] = a.y;
            d[4 * j + 2] = a.z;
            d[4 * j + 3] = a.w;
        }
    }

    int stride = is64 ? 2 : 1;
    #pragma unroll
    for (int k = 0; k < EPT; k++) {
        if ((d[k] & 31) == 31) {
            int g = d[k] >> 5;
            int src = p[(e + k) * stride];
            int pos = atomicAdd(&g_cnt[b][g], 1);
            if (pos < CAP) g_bucket[b][g][pos] = src;
        }
    }
}

// ---------------- K2: fused. 16 agg warps (1 task each) + s-split batched
// GEMV over all 512 threads + fused epilogue. launch_bounds(512,4) => <=32
// regs => 2048 thr/SM: all 8192 agg tasks run in wave 1.
__global__ __launch_bounds__(512, 4) void k2_fused(
    const float* __restrict__ upx, const float* __restrict__ dnx,
    const float* __restrict__ upW, const float* __restrict__ dnW,
    const float* __restrict__ upB, const float* __restrict__ dnB,
    const float* __restrict__ mlpW, const float* __restrict__ mlpB,
    float* __restrict__ out) {

    int g0 = blockIdx.x * GPB;
    int t  = threadIdx.x;
    int w  = t >> 5;
    int l  = t & 31;

    __shared__ int   sh_src[16][CAP];        // 4KB
    __shared__ float xt[2][SDIM][GPB];       // 4KB transposed xagg
    __shared__ float ph[2][GPB][HDIM];       // 8KB GEMV partials (s-half 1)
    __shared__ float sig[2][GPB][HDIM];      // 8KB sigmoid outputs

    // ---- phase 1: aggregation, one (branch, graph) task per warp ----
    {
        int b  = w >> 3;                     // warps 0-7: up, 8-15: down
        int gi = w & 7;
        int g  = g0 + gi;
        const float* x = b ? dnx : upx;

        int n = g_cnt[b][g];
        if (l == 0) g_cnt[b][g] = 0;         // restore zero-invariant
        if (n > CAP) n = CAP;
        ((int2*)sh_src[w])[l] = ((const int2*)g_bucket[b][g])[l];
        __syncwarp();

        // folded attention weights: lane l owns dims {2l, 2l+1}
        float2 ws = ((const float2*)g_wsd[b][0])[l];
        float2 wd = ((const float2*)g_wsd[b][1])[l];

        // a_dst for the terminal node of this graph
        float2 xd = ((const float2*)(x + (g * NPG + NPG - 1) * SDIM))[l];
        float part = xd.x * wd.x + xd.y * wd.y;
        #pragma unroll
        for (int o = 16; o; o >>= 1) part += __shfl_xor_sync(0xffffffffu, part, o);
        float a_dst = part;

        // un-shifted softmax aggregation (logits O(10); exp safe in fp32)
        float denom = 0.f, acc0 = 0.f, acc1 = 0.f;
        for (int i = 0; i < n; i++) {
            int src = sh_src[w][i];
            float2 xv = ((const float2*)(x + src * SDIM))[l];   // one LDG.64
            float ps = xv.x * ws.x + xv.y * ws.y;
            #pragma unroll
            for (int o = 16; o; o >>= 1) ps += __shfl_xor_sync(0xffffffffu, ps, o);
            float ev = ps + a_dst;
            ev = ev > 0.f ? ev : 0.2f * ev;  // leaky_relu(0.2)
            float q = __expf(ev);
            denom += q;
            acc0 += q * xv.x;
            acc1 += q * xv.y;
        }
        float inv = 1.f / (denom + 1e-16f);
        xt[b][2 * l][gi]     = acc0 * inv;   // transposed for batched GEMV
        xt[b][2 * l + 1][gi] = acc1 * inv;
    }
    __syncthreads();

    // ---- phase 2: batched GEMV split over ALL 512 threads.
    // thread = (s-half, branch, h); each W element FMAed against 8 graphs. ----
    {
        int sh = t >> 8;                     // s half: 0 or 1
        int r  = t & 255;
        int b  = r >> 7;
        int h  = r & 127;
        const float* W = b ? dnW : upW;

        float ho[GPB];
        #pragma unroll
        for (int gi = 0; gi < GPB; gi++) ho[gi] = 0.f;

        int s0 = sh * (SDIM / 2);
        #pragma unroll 8
        for (int s = s0; s < s0 + SDIM / 2; s++) {
            float wv = W[s * HDIM + h];               // coalesced
            float4 xa = *(const float4*)&xt[b][s][0]; // broadcast LDS
            float4 xb = *(const float4*)&xt[b][s][4];
            ho[0] += wv * xa.x; ho[1] += wv * xa.y;
            ho[2] += wv * xa.z; ho[3] += wv * xa.w;
            ho[4] += wv * xb.x; ho[5] += wv * xb.y;
            ho[6] += wv * xb.z; ho[7] += wv * xb.w;
        }
        if (sh == 1) {
            #pragma unroll
            for (int gi = 0; gi < GPB; gi++) ph[b][gi][h] = ho[gi];
        }
        __syncthreads();
        if (sh == 0) {
            float bv = (b ? dnB : upB)[h];
            #pragma unroll
            for (int gi = 0; gi < GPB; gi++)
                sig[b][gi][h] = 1.f / (1.f + __expf(-(ho[gi] + ph[b][gi][h] + bv)));
        }
    }
    __syncthreads();

    // ---- phase 3: fused epilogue, warps 0..7 -> graph g0+w ----
    if (w < GPB) {
        float4 s0 = ((const float4*)sig[0][w])[l];
        float4 s1 = ((const float4*)sig[1][w])[l];
        float4 mw = ((const float4*)mlpW)[l];
        float s = s0.x * s1.x * mw.x + s0.y * s1.y * mw.y
                + s0.z * s1.z * mw.z + s0.w * s1.w * mw.w;
        #pragma unroll
        for (int o = 16; o; o >>= 1) s += __shfl_xor_sync(0xffffffffu, s, o);
        if (l == 0) out[g0 + w] = s + mlpB[0];
    }
}

// ---------------- launch ----------------------------------------------------
extern "C" void kernel_launch(void* const* d_in, const int* in_sizes, int n_in,
                              void* d_out, int out_size) {
    const float* up_x  = (const float*)d_in[0];
    const int*   up_e  = (const int*)  d_in[1];
    const float* dn_x  = (const float*)d_in[3];
    const int*   dn_e  = (const int*)  d_in[4];
    const float* upW   = (const float*)d_in[6];
    const float* upAs  = (const float*)d_in[7];
    const float* upAd  = (const float*)d_in[8];
    const float* upB   = (const float*)d_in[9];
    const float* dnW   = (const float*)d_in[10];
    const float* dnAs  = (const float*)d_in[11];
    const float* dnAd  = (const float*)d_in[12];
    const float* dnB   = (const float*)d_in[13];
    const float* mlpW  = (const float*)d_in[14];
    const float* mlpB  = (const float*)d_in[15];
    float* out = (float*)d_out;

    // int64 edge tensors arrive as int32 words with doubled element count:
    // 2*2*NE = 4*NE words vs 2*NE for true int32.
    int is64_up = (in_sizes[1] >= 4 * NE) ? 1 : 0;
    int is64_dn = (in_sizes[4] >= 4 * NE) ? 1 : 0;

    k1_filter<<<NB_EDGE + NB_FOLD, 256>>>(up_e, dn_e, is64_up, is64_dn,
                                          upW, upAs, upAd, dnW, dnAs, dnAd);
    k2_fused<<<NG / GPB, 512>>>(up_x, dn_x, upW, dnW, upB, dnB, mlpW, mlpB, out);
}